// round 3
// baseline (speedup 1.0000x reference)
#include <cuda_runtime.h>
#include <math.h>

// Problem constants
#define TT 256
#define BB 128
#define EE 512
#define HH 1024
#define G3 3072   // 3*H

// ---------------------------------------------------------------------------
// Scratch (device globals; zero-init bss — no dynamic allocation anywhere)
// ---------------------------------------------------------------------------
__device__ float g_GI0[(size_t)TT * BB * G3];  // precomputed x @ W_ih0^T + b_ih0
__device__ float g_h0[2][BB * HH];             // layer0 hidden, ping-pong by t parity
__device__ float g_h1[2][BB * HH];             // layer1 hidden
__device__ float g_x1[2][BB * HH];             // layer0 output (layer1 input), by t parity

// ---------------------------------------------------------------------------
// Zero initial hidden states (h in buffer [0] at t=0)
// ---------------------------------------------------------------------------
__global__ void zero_h_kernel() {
    int idx = blockIdx.x * blockDim.x + threadIdx.x;   // 128*256 = 32768 = BB*HH/4
    float4 z = make_float4(0.f, 0.f, 0.f, 0.f);
    ((float4*)g_h0[0])[idx] = z;
    ((float4*)g_h1[0])[idx] = z;
}

// ---------------------------------------------------------------------------
// Precompute GI0[t,b,:] = x[t,b,:] @ W_ih0^T + b_ih0  (skips inactive tiles)
// Tile: 64 (rows within one t) x 64 (gate cols), K=512.  256 threads, 4x4/thread.
// ---------------------------------------------------------------------------
__global__ __launch_bounds__(256) void gi0_kernel(
    const float* __restrict__ x, const float* __restrict__ W,
    const float* __restrict__ bias, const int* __restrict__ bs)
{
    __shared__ __align__(16) float As[32][68];  // [k][m]
    __shared__ __align__(16) float Bs[32][68];  // [k][n]

    const int nbase = blockIdx.x * 64;
    const int trow  = blockIdx.y;          // 0..511
    const int t     = trow >> 1;
    const int mb    = (trow & 1) << 6;     // 0 or 64
    if (mb >= bs[t]) return;               // packed-seq: rows never used downstream

    const int tid = threadIdx.x;
    const int tx  = tid & 15;              // m-group
    const int ty  = tid >> 4;              // n-group

    float acc[4][4];
#pragma unroll
    for (int i = 0; i < 4; i++)
#pragma unroll
        for (int j = 0; j < 4; j++) acc[i][j] = 0.f;

    const float* Arow = x + (size_t)(t * BB + mb) * EE;

    for (int k0 = 0; k0 < EE; k0 += 32) {
#pragma unroll
        for (int r = 0; r < 2; r++) {
            int idx = tid + r * 256;
            int m = idx >> 3, c4 = (idx & 7) * 4;
            float4 v = *(const float4*)&Arow[(size_t)m * EE + k0 + c4];
            As[c4 + 0][m] = v.x; As[c4 + 1][m] = v.y;
            As[c4 + 2][m] = v.z; As[c4 + 3][m] = v.w;
        }
#pragma unroll
        for (int r = 0; r < 2; r++) {
            int idx = tid + r * 256;
            int n = idx >> 3, c4 = (idx & 7) * 4;
            float4 v = *(const float4*)&W[(size_t)(nbase + n) * EE + k0 + c4];
            Bs[c4 + 0][n] = v.x; Bs[c4 + 1][n] = v.y;
            Bs[c4 + 2][n] = v.z; Bs[c4 + 3][n] = v.w;
        }
        __syncthreads();
#pragma unroll
        for (int k = 0; k < 32; k++) {
            float4 a = *(const float4*)&As[k][tx * 4];
            float4 b = *(const float4*)&Bs[k][ty * 4];
            const float* ap = (const float*)&a;
            const float* bp = (const float*)&b;
#pragma unroll
            for (int i = 0; i < 4; i++)
#pragma unroll
                for (int j = 0; j < 4; j++)
                    acc[i][j] = fmaf(ap[i], bp[j], acc[i][j]);
        }
        __syncthreads();
    }

    const int n = nbase + ty * 4;
    float4 bv = *(const float4*)&bias[n];
#pragma unroll
    for (int i = 0; i < 4; i++) {
        int m = tx * 4 + i;
        size_t row = (size_t)(t * BB + mb + m);
        float4 o;
        o.x = acc[i][0] + bv.x; o.y = acc[i][1] + bv.y;
        o.z = acc[i][2] + bv.z; o.w = acc[i][3] + bv.w;
        *(float4*)&g_GI0[row * G3 + n] = o;
    }
}

// ---------------------------------------------------------------------------
// Per (k4, acc) micro-MMA: 4 k-steps, 2 m x 2 j x 3 gates
// ---------------------------------------------------------------------------
__device__ __forceinline__ void mma_micro(const float* __restrict__ ws,
                                          const float (*sm)[66],
                                          int k4, int lane, int jl,
                                          float acc[2][2][3])
{
    float2 a[4];
#pragma unroll
    for (int i = 0; i < 4; i++)
        a[i] = *(const float2*)&sm[k4 + i][2 * lane];
#pragma unroll
    for (int ji = 0; ji < 2; ji++) {
#pragma unroll
        for (int g = 0; g < 3; g++) {
            float4 w = *(const float4*)&ws[(g * 16 + jl + ji) * 32 + k4];
            const float* wp = (const float*)&w;
#pragma unroll
            for (int i = 0; i < 4; i++) {
                acc[0][ji][g] = fmaf(a[i].x, wp[i], acc[0][ji][g]);
                acc[1][ji][g] = fmaf(a[i].y, wp[i], acc[1][ji][g]);
            }
        }
    }
}

__device__ __forceinline__ float sigf(float v) {
    return 1.f / (1.f + __expf(-v));
}

// ---------------------------------------------------------------------------
// Fused pipelined step: blocks [0,128) do layer0 @ t=k; blocks [128,256) do
// layer1 @ t=k-1 (inputs of layer1@t-1 were produced by the previous kernel).
// Each CTA: 64 rows x 16 hidden cols x 3 gates; inactive tiles copy h through.
// ---------------------------------------------------------------------------
__global__ __launch_bounds__(256) void fused_step(
    const float* __restrict__ Whh0, const float* __restrict__ Wih1,
    const float* __restrict__ Whh1,
    const float* __restrict__ bhh0, const float* __restrict__ bih1,
    const float* __restrict__ bhh1,
    const int* __restrict__ bs, int kk)
{
    __shared__ __align__(16) float hs[32][66];
    __shared__ __align__(16) float xs[32][66];
    __shared__ __align__(16) float ws_h[48 * 32];
    __shared__ __align__(16) float ws_i[48 * 32];

    const int c  = blockIdx.x;
    const bool l1 = (c >= 128);
    const int t  = l1 ? (kk - 1) : kk;
    if (t < 0 || t >= TT) return;

    const int cc    = l1 ? (c - 128) : c;
    const int jbase = (cc >> 1) * 16;
    const int mbase = (cc & 1) << 6;
    const int active = bs[t];
    const int p = t & 1;

    const float* hold = l1 ? g_h0[0] /*placeholder*/ : g_h0[0];
    hold = l1 ? g_h1[p] : g_h0[p];
    float* hnew = l1 ? g_h1[p ^ 1] : g_h0[p ^ 1];

    const int tid = threadIdx.x;

    if (mbase >= active) {
        // inactive tile: h passes through unchanged into the ping-pong buffer
        int m  = tid >> 2;
        int j4 = tid & 3;
        const float4* src = (const float4*)(hold + (size_t)(mbase + m) * HH + jbase);
        float4* dst = (float4*)(hnew + (size_t)(mbase + m) * HH + jbase);
        dst[j4] = src[j4];
        return;
    }

    const int lane = tid & 31;
    const int warp = tid >> 5;
    const int jl   = 2 * warp;           // local j base (0..14)

    float acch[2][2][3];
    float acci[2][2][3];
#pragma unroll
    for (int a = 0; a < 2; a++)
#pragma unroll
        for (int b = 0; b < 2; b++)
#pragma unroll
            for (int g = 0; g < 3; g++) { acch[a][b][g] = 0.f; acci[a][b][g] = 0.f; }

    const float* Wh = l1 ? Whh1 : Whh0;
    const float* Ai = g_x1[p];           // used only when l1

    for (int k0 = 0; k0 < HH; k0 += 32) {
        // h tile (64 m x 32 k), stored transposed [k][m]
#pragma unroll
        for (int r = 0; r < 2; r++) {
            int idx = tid + r * 256;
            int m = idx >> 3, c4 = (idx & 7) * 4;
            float4 v = *(const float4*)&hold[(size_t)(mbase + m) * HH + k0 + c4];
            hs[c4 + 0][m] = v.x; hs[c4 + 1][m] = v.y;
            hs[c4 + 2][m] = v.z; hs[c4 + 3][m] = v.w;
        }
        // W_hh tile: 48 gate-rows x 32 k
#pragma unroll
        for (int base = 0; base < 384; base += 256) {
            int idx = tid + base;
            if (idx < 384) {
                int r = idx >> 3, c4 = (idx & 7) * 4;
                int grow = jbase + (r & 15) + (r >> 4) * HH;
                *(float4*)&ws_h[r * 32 + c4] =
                    *(const float4*)&Wh[(size_t)grow * HH + k0 + c4];
            }
        }
        if (l1) {
#pragma unroll
            for (int r = 0; r < 2; r++) {
                int idx = tid + r * 256;
                int m = idx >> 3, c4 = (idx & 7) * 4;
                float4 v = *(const float4*)&Ai[(size_t)(mbase + m) * HH + k0 + c4];
                xs[c4 + 0][m] = v.x; xs[c4 + 1][m] = v.y;
                xs[c4 + 2][m] = v.z; xs[c4 + 3][m] = v.w;
            }
#pragma unroll
            for (int base = 0; base < 384; base += 256) {
                int idx = tid + base;
                if (idx < 384) {
                    int r = idx >> 3, c4 = (idx & 7) * 4;
                    int grow = jbase + (r & 15) + (r >> 4) * HH;
                    *(float4*)&ws_i[r * 32 + c4] =
                        *(const float4*)&Wih1[(size_t)grow * HH + k0 + c4];
                }
            }
        }
        __syncthreads();

        if (l1) {
#pragma unroll 4
            for (int k4 = 0; k4 < 32; k4 += 4) {
                mma_micro(ws_h, hs, k4, lane, jl, acch);
                mma_micro(ws_i, xs, k4, lane, jl, acci);
            }
        } else {
#pragma unroll 4
            for (int k4 = 0; k4 < 32; k4 += 4) {
                mma_micro(ws_h, hs, k4, lane, jl, acch);
            }
        }
        __syncthreads();
    }

    // ---- gate math + state update ----
    const float* bh = l1 ? bhh1 : bhh0;
#pragma unroll
    for (int mi = 0; mi < 2; mi++) {
        int m = mbase + 2 * lane + mi;
#pragma unroll
        for (int ji = 0; ji < 2; ji++) {
            int j = jbase + jl + ji;
            float gr, gz, gn;
            if (!l1) {
                const float* gi = g_GI0 + (size_t)(t * BB + m) * G3;
                gr = gi[j]; gz = gi[HH + j]; gn = gi[2 * HH + j];
            } else {
                gr = acci[mi][ji][0] + bih1[j];
                gz = acci[mi][ji][1] + bih1[HH + j];
                gn = acci[mi][ji][2] + bih1[2 * HH + j];
            }
            float hr  = acch[mi][ji][0] + bh[j];
            float hz  = acch[mi][ji][1] + bh[HH + j];
            float hnn = acch[mi][ji][2] + bh[2 * HH + j];

            float r  = sigf(gr + hr);
            float z  = sigf(gz + hz);
            float nv = tanhf(fmaf(r, hnn, gn));
            float hp = hold[(size_t)m * HH + j];
            float hv = fmaf(z, hp - nv, nv);          // (1-z)*n + z*h

            hnew[(size_t)m * HH + j] = (m < active) ? hv : hp;
            if (!l1) g_x1[p][(size_t)m * HH + j] = hv; // layer1 input is UNMASKED hn
        }
    }
}

// ---------------------------------------------------------------------------
// Final gather: out[l, b, :] = h_l[unsorted_indices[b], :]
// ---------------------------------------------------------------------------
__global__ void gather_kernel(const int* __restrict__ u, float* __restrict__ out) {
    int idx = blockIdx.x * blockDim.x + threadIdx.x;  // 2*128*256 float4 = 65536
    int l   = idx / (BB * (HH / 4));
    int rem = idx % (BB * (HH / 4));
    int b   = rem / (HH / 4);
    int j4  = rem % (HH / 4);
    const float* src = (l ? g_h1[0] : g_h0[0]) + (size_t)u[b] * HH;
    ((float4*)out)[idx] = ((const float4*)src)[j4];
}

// ---------------------------------------------------------------------------
extern "C" void kernel_launch(void* const* d_in, const int* in_sizes, int n_in,
                              void* d_out, int out_size) {
    const float* x    = (const float*)d_in[0];
    const float* Wih0 = (const float*)d_in[1];
    const float* Whh0 = (const float*)d_in[2];
    const float* bih0 = (const float*)d_in[3];
    // d_in[4] = b_hh0
    const float* bhh0 = (const float*)d_in[4];
    const float* Wih1 = (const float*)d_in[5];
    const float* Whh1 = (const float*)d_in[6];
    const float* bih1 = (const float*)d_in[7];
    const float* bhh1 = (const float*)d_in[8];
    const int*   bs   = (const int*)d_in[9];
    const int*   ui   = (const int*)d_in[10];

    zero_h_kernel<<<128, 256>>>();
    gi0_kernel<<<dim3(48, 2 * TT), 256>>>(x, Wih0, bih0, bs);
    for (int k = 0; k <= TT; k++)
        fused_step<<<256, 256>>>(Whh0, Wih1, Whh1, bhh0, bih1, bhh1, bs, k);
    gather_kernel<<<256, 256>>>(ui, (float*)d_out);
}

// round 4
// speedup vs baseline: 1.0014x; 1.0014x over previous
#include <cuda_runtime.h>
#include <math.h>

// Problem constants
#define TT 256
#define BB 128
#define EE 512
#define HH 1024
#define G3 3072   // 3*H

// ---------------------------------------------------------------------------
// Scratch (device globals; zero-init bss — no dynamic allocation anywhere)
// ---------------------------------------------------------------------------
__device__ float g_GI0[(size_t)TT * BB * G3];  // precomputed x @ W_ih0^T + b_ih0
__device__ float g_h0[2][BB * HH];             // layer0 hidden, ping-pong by t parity
__device__ float g_h1[2][BB * HH];             // layer1 hidden
__device__ float g_x1[2][BB * HH];             // layer0 output (layer1 input), by t parity

// ---------------------------------------------------------------------------
// Zero initial hidden states (h in buffer [0] at t=0)
// ---------------------------------------------------------------------------
__global__ void zero_h_kernel() {
    int idx = blockIdx.x * blockDim.x + threadIdx.x;   // 128*256 = 32768 = BB*HH/4
    float4 z = make_float4(0.f, 0.f, 0.f, 0.f);
    ((float4*)g_h0[0])[idx] = z;
    ((float4*)g_h1[0])[idx] = z;
}

// ---------------------------------------------------------------------------
// Precompute GI0[t,b,:] = x[t,b,:] @ W_ih0^T + b_ih0  (skips inactive tiles)
// Tile: 64 (rows within one t) x 64 (gate cols), K=512.  256 threads, 4x4/thread.
// ---------------------------------------------------------------------------
__global__ __launch_bounds__(256) void gi0_kernel(
    const float* __restrict__ x, const float* __restrict__ W,
    const float* __restrict__ bias, const int* __restrict__ bs)
{
    __shared__ __align__(16) float As[32][68];  // [k][m]
    __shared__ __align__(16) float Bs[32][68];  // [k][n]

    const int nbase = blockIdx.x * 64;
    const int trow  = blockIdx.y;          // 0..511
    const int t     = trow >> 1;
    const int mb    = (trow & 1) << 6;     // 0 or 64
    if (mb >= bs[t]) return;               // packed-seq: rows never used downstream

    const int tid = threadIdx.x;
    const int tx  = tid & 15;              // m-group
    const int ty  = tid >> 4;              // n-group

    float acc[4][4];
#pragma unroll
    for (int i = 0; i < 4; i++)
#pragma unroll
        for (int j = 0; j < 4; j++) acc[i][j] = 0.f;

    const float* Arow = x + (size_t)(t * BB + mb) * EE;

    for (int k0 = 0; k0 < EE; k0 += 32) {
#pragma unroll
        for (int r = 0; r < 2; r++) {
            int idx = tid + r * 256;
            int m = idx >> 3, c4 = (idx & 7) * 4;
            float4 v = *(const float4*)&Arow[(size_t)m * EE + k0 + c4];
            As[c4 + 0][m] = v.x; As[c4 + 1][m] = v.y;
            As[c4 + 2][m] = v.z; As[c4 + 3][m] = v.w;
        }
#pragma unroll
        for (int r = 0; r < 2; r++) {
            int idx = tid + r * 256;
            int n = idx >> 3, c4 = (idx & 7) * 4;
            float4 v = *(const float4*)&W[(size_t)(nbase + n) * EE + k0 + c4];
            Bs[c4 + 0][n] = v.x; Bs[c4 + 1][n] = v.y;
            Bs[c4 + 2][n] = v.z; Bs[c4 + 3][n] = v.w;
        }
        __syncthreads();
#pragma unroll
        for (int k = 0; k < 32; k++) {
            float4 a = *(const float4*)&As[k][tx * 4];
            float4 b = *(const float4*)&Bs[k][ty * 4];
            const float* ap = (const float*)&a;
            const float* bp = (const float*)&b;
#pragma unroll
            for (int i = 0; i < 4; i++)
#pragma unroll
                for (int j = 0; j < 4; j++)
                    acc[i][j] = fmaf(ap[i], bp[j], acc[i][j]);
        }
        __syncthreads();
    }

    const int n = nbase + ty * 4;
    float4 bv = *(const float4*)&bias[n];
#pragma unroll
    for (int i = 0; i < 4; i++) {
        int m = tx * 4 + i;
        size_t row = (size_t)(t * BB + mb + m);
        float4 o;
        o.x = acc[i][0] + bv.x; o.y = acc[i][1] + bv.y;
        o.z = acc[i][2] + bv.z; o.w = acc[i][3] + bv.w;
        *(float4*)&g_GI0[row * G3 + n] = o;
    }
}

// ---------------------------------------------------------------------------
// Per (k4, acc) micro-MMA: 4 k-steps, 2 m x 2 j x 3 gates
// ---------------------------------------------------------------------------
__device__ __forceinline__ void mma_micro(const float* __restrict__ ws,
                                          const float (*sm)[66],
                                          int k4, int lane, int jl,
                                          float acc[2][2][3])
{
    float2 a[4];
#pragma unroll
    for (int i = 0; i < 4; i++)
        a[i] = *(const float2*)&sm[k4 + i][2 * lane];
#pragma unroll
    for (int ji = 0; ji < 2; ji++) {
#pragma unroll
        for (int g = 0; g < 3; g++) {
            float4 w = *(const float4*)&ws[(g * 16 + jl + ji) * 32 + k4];
            const float* wp = (const float*)&w;
#pragma unroll
            for (int i = 0; i < 4; i++) {
                acc[0][ji][g] = fmaf(a[i].x, wp[i], acc[0][ji][g]);
                acc[1][ji][g] = fmaf(a[i].y, wp[i], acc[1][ji][g]);
            }
        }
    }
}

__device__ __forceinline__ float sigf(float v) {
    return 1.f / (1.f + __expf(-v));
}

// ---------------------------------------------------------------------------
// Fused pipelined step: blocks [0,128) do layer0 @ t=k; blocks [128,256) do
// layer1 @ t=k-1 (inputs of layer1@t-1 were produced by the previous kernel).
// Each CTA: 64 rows x 16 hidden cols x 3 gates; inactive tiles copy h through.
// ---------------------------------------------------------------------------
__global__ __launch_bounds__(256) void fused_step(
    const float* __restrict__ Whh0, const float* __restrict__ Wih1,
    const float* __restrict__ Whh1,
    const float* __restrict__ bhh0, const float* __restrict__ bih1,
    const float* __restrict__ bhh1,
    const int* __restrict__ bs, int kk)
{
    __shared__ __align__(16) float hs[32][66];
    __shared__ __align__(16) float xs[32][66];
    __shared__ __align__(16) float ws_h[48 * 32];
    __shared__ __align__(16) float ws_i[48 * 32];

    const int c  = blockIdx.x;
    const bool l1 = (c >= 128);
    const int t  = l1 ? (kk - 1) : kk;
    if (t < 0 || t >= TT) return;

    const int cc    = l1 ? (c - 128) : c;
    const int jbase = (cc >> 1) * 16;
    const int mbase = (cc & 1) << 6;
    const int active = bs[t];
    const int p = t & 1;

    const float* hold = l1 ? g_h0[0] /*placeholder*/ : g_h0[0];
    hold = l1 ? g_h1[p] : g_h0[p];
    float* hnew = l1 ? g_h1[p ^ 1] : g_h0[p ^ 1];

    const int tid = threadIdx.x;

    if (mbase >= active) {
        // inactive tile: h passes through unchanged into the ping-pong buffer
        int m  = tid >> 2;
        int j4 = tid & 3;
        const float4* src = (const float4*)(hold + (size_t)(mbase + m) * HH + jbase);
        float4* dst = (float4*)(hnew + (size_t)(mbase + m) * HH + jbase);
        dst[j4] = src[j4];
        return;
    }

    const int lane = tid & 31;
    const int warp = tid >> 5;
    const int jl   = 2 * warp;           // local j base (0..14)

    float acch[2][2][3];
    float acci[2][2][3];
#pragma unroll
    for (int a = 0; a < 2; a++)
#pragma unroll
        for (int b = 0; b < 2; b++)
#pragma unroll
            for (int g = 0; g < 3; g++) { acch[a][b][g] = 0.f; acci[a][b][g] = 0.f; }

    const float* Wh = l1 ? Whh1 : Whh0;
    const float* Ai = g_x1[p];           // used only when l1

    for (int k0 = 0; k0 < HH; k0 += 32) {
        // h tile (64 m x 32 k), stored transposed [k][m]
#pragma unroll
        for (int r = 0; r < 2; r++) {
            int idx = tid + r * 256;
            int m = idx >> 3, c4 = (idx & 7) * 4;
            float4 v = *(const float4*)&hold[(size_t)(mbase + m) * HH + k0 + c4];
            hs[c4 + 0][m] = v.x; hs[c4 + 1][m] = v.y;
            hs[c4 + 2][m] = v.z; hs[c4 + 3][m] = v.w;
        }
        // W_hh tile: 48 gate-rows x 32 k
#pragma unroll
        for (int base = 0; base < 384; base += 256) {
            int idx = tid + base;
            if (idx < 384) {
                int r = idx >> 3, c4 = (idx & 7) * 4;
                int grow = jbase + (r & 15) + (r >> 4) * HH;
                *(float4*)&ws_h[r * 32 + c4] =
                    *(const float4*)&Wh[(size_t)grow * HH + k0 + c4];
            }
        }
        if (l1) {
#pragma unroll
            for (int r = 0; r < 2; r++) {
                int idx = tid + r * 256;
                int m = idx >> 3, c4 = (idx & 7) * 4;
                float4 v = *(const float4*)&Ai[(size_t)(mbase + m) * HH + k0 + c4];
                xs[c4 + 0][m] = v.x; xs[c4 + 1][m] = v.y;
                xs[c4 + 2][m] = v.z; xs[c4 + 3][m] = v.w;
            }
#pragma unroll
            for (int base = 0; base < 384; base += 256) {
                int idx = tid + base;
                if (idx < 384) {
                    int r = idx >> 3, c4 = (idx & 7) * 4;
                    int grow = jbase + (r & 15) + (r >> 4) * HH;
                    *(float4*)&ws_i[r * 32 + c4] =
                        *(const float4*)&Wih1[(size_t)grow * HH + k0 + c4];
                }
            }
        }
        __syncthreads();

        if (l1) {
#pragma unroll 4
            for (int k4 = 0; k4 < 32; k4 += 4) {
                mma_micro(ws_h, hs, k4, lane, jl, acch);
                mma_micro(ws_i, xs, k4, lane, jl, acci);
            }
        } else {
#pragma unroll 4
            for (int k4 = 0; k4 < 32; k4 += 4) {
                mma_micro(ws_h, hs, k4, lane, jl, acch);
            }
        }
        __syncthreads();
    }

    // ---- gate math + state update ----
    const float* bh = l1 ? bhh1 : bhh0;
#pragma unroll
    for (int mi = 0; mi < 2; mi++) {
        int m = mbase + 2 * lane + mi;
#pragma unroll
        for (int ji = 0; ji < 2; ji++) {
            int j = jbase + jl + ji;
            float gr, gz, gn;
            if (!l1) {
                const float* gi = g_GI0 + (size_t)(t * BB + m) * G3;
                gr = gi[j]; gz = gi[HH + j]; gn = gi[2 * HH + j];
            } else {
                gr = acci[mi][ji][0] + bih1[j];
                gz = acci[mi][ji][1] + bih1[HH + j];
                gn = acci[mi][ji][2] + bih1[2 * HH + j];
            }
            float hr  = acch[mi][ji][0] + bh[j];
            float hz  = acch[mi][ji][1] + bh[HH + j];
            float hnn = acch[mi][ji][2] + bh[2 * HH + j];

            float r  = sigf(gr + hr);
            float z  = sigf(gz + hz);
            float nv = tanhf(fmaf(r, hnn, gn));
            float hp = hold[(size_t)m * HH + j];
            float hv = fmaf(z, hp - nv, nv);          // (1-z)*n + z*h

            hnew[(size_t)m * HH + j] = (m < active) ? hv : hp;
            if (!l1) g_x1[p][(size_t)m * HH + j] = hv; // layer1 input is UNMASKED hn
        }
    }
}

// ---------------------------------------------------------------------------
// Final gather: out[l, b, :] = h_l[unsorted_indices[b], :]
// ---------------------------------------------------------------------------
__global__ void gather_kernel(const int* __restrict__ u, float* __restrict__ out) {
    int idx = blockIdx.x * blockDim.x + threadIdx.x;  // 2*128*256 float4 = 65536
    int l   = idx / (BB * (HH / 4));
    int rem = idx % (BB * (HH / 4));
    int b   = rem / (HH / 4);
    int j4  = rem % (HH / 4);
    const float* src = (l ? g_h1[0] : g_h0[0]) + (size_t)u[b] * HH;
    ((float4*)out)[idx] = ((const float4*)src)[j4];
}

// ---------------------------------------------------------------------------
extern "C" void kernel_launch(void* const* d_in, const int* in_sizes, int n_in,
                              void* d_out, int out_size) {
    const float* x    = (const float*)d_in[0];
    const float* Wih0 = (const float*)d_in[1];
    const float* Whh0 = (const float*)d_in[2];
    const float* bih0 = (const float*)d_in[3];
    // d_in[4] = b_hh0
    const float* bhh0 = (const float*)d_in[4];
    const float* Wih1 = (const float*)d_in[5];
    const float* Whh1 = (const float*)d_in[6];
    const float* bih1 = (const float*)d_in[7];
    const float* bhh1 = (const float*)d_in[8];
    const int*   bs   = (const int*)d_in[9];
    const int*   ui   = (const int*)d_in[10];

    zero_h_kernel<<<128, 256>>>();
    gi0_kernel<<<dim3(48, 2 * TT), 256>>>(x, Wih0, bih0, bs);
    for (int k = 0; k <= TT; k++)
        fused_step<<<256, 256>>>(Whh0, Wih1, Whh1, bhh0, bih1, bhh1, bs, k);
    gather_kernel<<<256, 256>>>(ui, (float*)d_out);
}

// round 6
// speedup vs baseline: 1.5257x; 1.5236x over previous
#include <cuda_runtime.h>
#include <cuda_bf16.h>
#include <stdint.h>
#include <math.h>

#define TT 256
#define BB 128
#define EE 512
#define HH 1024
#define G3 3072
#define KC 32            // K per stage (bf16 elems)
#define NSTG 96          // 3 passes * (1024/32)
#define SA 80            // smem row stride bytes (32 bf16 = 64B data + 16B pad)

// uniform per-stage smem frame (bytes)
#define OFF_AH 0
#define OFF_AI 5120
#define OFF_BH 10240     // l0: 48 rows (3840B) ; l1: 24 rows (1920B)
#define OFF_BI 14080
#define STG    16000
#define SMEM_B (2*STG)   // 32000 bytes static

// ---------------- device scratch (bss) ----------------
__device__ float g_GI0[(size_t)TT * BB * G3];
__device__ float g_h0f[2][BB * HH];
__device__ float g_h1f[2][BB * HH];
__device__ __nv_bfloat16 g_h0hi[2][BB*HH], g_h0lo[2][BB*HH];
__device__ __nv_bfloat16 g_h1hi[2][BB*HH], g_h1lo[2][BB*HH];
__device__ __nv_bfloat16 g_x1hi[2][BB*HH], g_x1lo[2][BB*HH];
__device__ __nv_bfloat16 g_Whi[3][(size_t)G3*HH];   // 0=Whh0 1=Wih1 2=Whh1
__device__ __nv_bfloat16 g_Wlo[3][(size_t)G3*HH];

// ---------------- helpers ----------------
__device__ __forceinline__ void cpa16(uint32_t dst, const void* src){
    asm volatile("cp.async.cg.shared.global [%0], [%1], 16;" :: "r"(dst), "l"(src));
}
__device__ __forceinline__ void cpa_commit(){ asm volatile("cp.async.commit_group;"); }
__device__ __forceinline__ void cpa_wait1(){ asm volatile("cp.async.wait_group 1;"); }
__device__ __forceinline__ void cpa_wait0(){ asm volatile("cp.async.wait_group 0;"); }

#define MMA16816(c, a, b0, b1) \
    asm volatile("mma.sync.aligned.m16n8k16.row.col.f32.bf16.bf16.f32 " \
        "{%0,%1,%2,%3},{%4,%5,%6,%7},{%8,%9},{%0,%1,%2,%3};" \
        : "+f"((c)[0]),"+f"((c)[1]),"+f"((c)[2]),"+f"((c)[3]) \
        : "r"((a)[0]),"r"((a)[1]),"r"((a)[2]),"r"((a)[3]),"r"(b0),"r"(b1))

__device__ __forceinline__ float sigf(float v){ return 1.f/(1.f+__expf(-v)); }
__device__ __forceinline__ void split2(float v, __nv_bfloat16& hi, __nv_bfloat16& lo){
    hi = __float2bfloat16(v);
    lo = __float2bfloat16(v - __bfloat162float(hi));
}

// ---------------- init kernels ----------------
__global__ void zero_h_kernel() {
    int i = blockIdx.x*256 + threadIdx.x;  // grid 512 -> 131072 = BB*HH
    g_h0f[0][i]=0.f; g_h1f[0][i]=0.f;
    __nv_bfloat16 z = __float2bfloat16(0.f);
    g_h0hi[0][i]=z; g_h0lo[0][i]=z; g_h1hi[0][i]=z; g_h1lo[0][i]=z;
}
__global__ void split_w_kernel(const float* __restrict__ w0, const float* __restrict__ w1,
                               const float* __restrict__ w2) {
    size_t i = (size_t)blockIdx.x*256 + threadIdx.x;
    int m = blockIdx.y;
    const float* s = (m==0)? w0 : (m==1)? w1 : w2;
    __nv_bfloat16 hi, lo; split2(s[i], hi, lo);
    g_Whi[m][i]=hi; g_Wlo[m][i]=lo;
}

// ---------------- GI0 precompute (fp32, off critical path) ----------------
__global__ __launch_bounds__(256) void gi0_kernel(
    const float* __restrict__ x, const float* __restrict__ W,
    const float* __restrict__ bias, const int* __restrict__ bs)
{
    __shared__ __align__(16) float As[32][68];
    __shared__ __align__(16) float Bs[32][68];
    const int nbase = blockIdx.x * 64;
    const int trow = blockIdx.y;
    const int t = trow>>1, mb = (trow&1)<<6;
    if (mb >= bs[t]) return;
    const int tid = threadIdx.x, tx = tid&15, ty = tid>>4;
    float acc[4][4];
#pragma unroll
    for (int i=0;i<4;i++)
#pragma unroll
        for (int j=0;j<4;j++) acc[i][j]=0.f;
    const float* Arow = x + (size_t)(t*BB+mb)*EE;
    for (int k0=0;k0<EE;k0+=32) {
#pragma unroll
        for (int r=0;r<2;r++){
            int idx=tid+r*256, m=idx>>3, c4=(idx&7)*4;
            float4 v = *(const float4*)&Arow[(size_t)m*EE+k0+c4];
            As[c4][m]=v.x; As[c4+1][m]=v.y; As[c4+2][m]=v.z; As[c4+3][m]=v.w;
        }
#pragma unroll
        for (int r=0;r<2;r++){
            int idx=tid+r*256, n=idx>>3, c4=(idx&7)*4;
            float4 v = *(const float4*)&W[(size_t)(nbase+n)*EE+k0+c4];
            Bs[c4][n]=v.x; Bs[c4+1][n]=v.y; Bs[c4+2][n]=v.z; Bs[c4+3][n]=v.w;
        }
        __syncthreads();
#pragma unroll
        for (int k=0;k<32;k++){
            float4 a=*(const float4*)&As[k][tx*4];
            float4 b=*(const float4*)&Bs[k][ty*4];
            const float *ap=(const float*)&a, *bp=(const float*)&b;
#pragma unroll
            for (int i=0;i<4;i++)
#pragma unroll
                for (int j=0;j<4;j++) acc[i][j]=fmaf(ap[i],bp[j],acc[i][j]);
        }
        __syncthreads();
    }
    const int n = nbase + ty*4;
    float4 bv = *(const float4*)&bias[n];
#pragma unroll
    for (int i=0;i<4;i++){
        size_t row = (size_t)(t*BB+mb+tx*4+i);
        float4 o; o.x=acc[i][0]+bv.x; o.y=acc[i][1]+bv.y; o.z=acc[i][2]+bv.z; o.w=acc[i][3]+bv.w;
        *(float4*)&g_GI0[row*G3+n] = o;
    }
}

// ---------------- mma.sync fused step ----------------
// CTAs [0,128): layer0 @ t=kk : M64 x 16 hidden cols (48 gate cols, 6 n8-tiles)
// CTAs [128,384): layer1 @ t=kk-1 : M64 x 8 hidden cols, dual GEMMs (gi & gh)
__global__ __launch_bounds__(128, 3) void mma_step(
    const float* __restrict__ bhh0, const float* __restrict__ bih1,
    const float* __restrict__ bhh1, const int* __restrict__ bs, int kk)
{
    __shared__ __align__(16) char smem[SMEM_B];
    const int cta = blockIdx.x;
    const bool l1 = cta >= 128;
    const int t = l1 ? kk-1 : kk;
    if (t < 0 || t >= TT) return;
    const int p = t & 1;
    const int idx = l1 ? cta-128 : cta;
    const int jbase = l1 ? (idx>>1)*8 : (idx>>1)*16;   // hidden-col base
    const int mbase = (idx&1)*64;
    const int tid = threadIdx.x, wid = tid>>5, lane = tid&31;
    const int l4 = lane>>2, lm4 = lane&3;
    const int active = bs[t];

    const float* hpf_all = l1 ? g_h1f[p] : g_h0f[p];
    float* hnf_all = l1 ? g_h1f[p^1] : g_h0f[p^1];
    __nv_bfloat16* hhi_all = l1 ? g_h1hi[p^1] : g_h0hi[p^1];
    __nv_bfloat16* hlo_all = l1 ? g_h1lo[p^1] : g_h0lo[p^1];

    const int NCOL = l1 ? 8 : 16;
    if (mbase >= active) {
        // inactive tile: pass h through (fp32 + splits); x1 left stale (unused)
        const int tot = 64*NCOL;
        for (int i = tid; i < tot; i += 128) {
            int r = i / NCOL, c = i % NCOL;
            size_t off = (size_t)(mbase + r)*HH + jbase + c;
            float hv = hpf_all[off];
            hnf_all[off] = hv;
            __nv_bfloat16 hi, lo; split2(hv, hi, lo);
            hhi_all[off] = hi; hlo_all[off] = lo;
        }
        return;
    }

    // pass pointer tables
    const __nv_bfloat16 *Ah[3], *Wh[3], *Ai[3], *Wi[3];
    if (!l1) {
        Ah[0]=g_h0hi[p]; Ah[1]=g_h0hi[p]; Ah[2]=g_h0lo[p];
        Wh[0]=g_Whi[0];  Wh[1]=g_Wlo[0];  Wh[2]=g_Whi[0];
    } else {
        Ah[0]=g_h1hi[p]; Ah[1]=g_h1hi[p]; Ah[2]=g_h1lo[p];
        Wh[0]=g_Whi[2];  Wh[1]=g_Wlo[2];  Wh[2]=g_Whi[2];
        Ai[0]=g_x1hi[p]; Ai[1]=g_x1hi[p]; Ai[2]=g_x1lo[p];
        Wi[0]=g_Whi[1];  Wi[1]=g_Wlo[1];  Wi[2]=g_Whi[1];
    }

    const uint32_t smem_u = (uint32_t)__cvta_generic_to_shared(smem);

    // ---- stage loader ----
    auto load_stage = [&](int s){
        const int pass = s >> 5;
        const int k0 = (s & 31) * KC;
        const uint32_t st = smem_u + (s & 1) * STG;
        // A_h: 64 rows x 4 chunks = 256
        {
            const __nv_bfloat16* A = Ah[pass];
#pragma unroll
            for (int i = 0; i < 2; i++) {
                int cid = tid + i*128, r = cid>>2, c = cid&3;
                cpa16(st + OFF_AH + r*SA + c*16, A + (size_t)(mbase+r)*HH + k0 + c*8);
            }
        }
        if (!l1) {
            // B_h: 48 rows (3 gates x 16) x 4 chunks = 192
            const __nv_bfloat16* W = Wh[pass];
            {
                int cid = tid, r = cid>>2, c = cid&3;
                int wrow = (r>>4)*HH + jbase + (r&15);
                cpa16(st + OFF_BH + r*SA + c*16, W + (size_t)wrow*HH + k0 + c*8);
            }
            if (tid < 64) {
                int cid = tid + 128, r = cid>>2, c = cid&3;
                int wrow = (r>>4)*HH + jbase + (r&15);
                cpa16(st + OFF_BH + r*SA + c*16, W + (size_t)wrow*HH + k0 + c*8);
            }
        } else {
            const __nv_bfloat16* A = Ai[pass];
#pragma unroll
            for (int i = 0; i < 2; i++) {
                int cid = tid + i*128, r = cid>>2, c = cid&3;
                cpa16(st + OFF_AI + r*SA + c*16, A + (size_t)(mbase+r)*HH + k0 + c*8);
            }
            // B_h, B_i: 24 rows (3 gates x 8) x 4 chunks = 96 each
            if (tid < 96) {
                int r = tid>>2, c = tid&3;
                int wrow = (r>>3)*HH + jbase + (r&7);
                cpa16(st + OFF_BH + r*SA + c*16, Wh[pass] + (size_t)wrow*HH + k0 + c*8);
                cpa16(st + OFF_BI + r*SA + c*16, Wi[pass] + (size_t)wrow*HH + k0 + c*8);
            }
        }
        cpa_commit();
    };

    // accumulators
    float ch[6][4], ci[3][4];
#pragma unroll
    for (int i=0;i<6;i++)
#pragma unroll
        for (int j=0;j<4;j++) ch[i][j]=0.f;
#pragma unroll
    for (int i=0;i<3;i++)
#pragma unroll
        for (int j=0;j<4;j++) ci[i][j]=0.f;

    const int arow_off = (wid*16 + l4)*SA + lm4*4;   // A frag base (row, col) bytes
    const int brow_off = l4*SA + lm4*4;

    load_stage(0);
    for (int s = 0; s < NSTG; s++) {
        if (s+1 < NSTG) { load_stage(s+1); cpa_wait1(); }
        else            { cpa_wait0(); }
        __syncthreads();
        const char* st = smem + (s & 1) * STG;
        const char* bAH = st + OFF_AH + arow_off;
        const char* bBH = st + OFF_BH + brow_off;
        if (!l1) {
#pragma unroll
            for (int kc = 0; kc < 2; kc++) {
                uint32_t a[4];
                a[0] = *(const uint32_t*)(bAH + kc*32);
                a[1] = *(const uint32_t*)(bAH + kc*32 + 8*SA);
                a[2] = *(const uint32_t*)(bAH + kc*32 + 16);
                a[3] = *(const uint32_t*)(bAH + kc*32 + 8*SA + 16);
#pragma unroll
                for (int nt = 0; nt < 6; nt++) {
                    uint32_t b0 = *(const uint32_t*)(bBH + nt*8*SA + kc*32);
                    uint32_t b1 = *(const uint32_t*)(bBH + nt*8*SA + kc*32 + 16);
                    MMA16816(ch[nt], a, b0, b1);
                }
            }
        } else {
            const char* bAI = st + OFF_AI + arow_off;
            const char* bBI = st + OFF_BI + brow_off;
#pragma unroll
            for (int kc = 0; kc < 2; kc++) {
                uint32_t a[4], ai[4];
                a[0]  = *(const uint32_t*)(bAH + kc*32);
                a[1]  = *(const uint32_t*)(bAH + kc*32 + 8*SA);
                a[2]  = *(const uint32_t*)(bAH + kc*32 + 16);
                a[3]  = *(const uint32_t*)(bAH + kc*32 + 8*SA + 16);
                ai[0] = *(const uint32_t*)(bAI + kc*32);
                ai[1] = *(const uint32_t*)(bAI + kc*32 + 8*SA);
                ai[2] = *(const uint32_t*)(bAI + kc*32 + 16);
                ai[3] = *(const uint32_t*)(bAI + kc*32 + 8*SA + 16);
#pragma unroll
                for (int nt = 0; nt < 3; nt++) {
                    uint32_t b0 = *(const uint32_t*)(bBH + nt*8*SA + kc*32);
                    uint32_t b1 = *(const uint32_t*)(bBH + nt*8*SA + kc*32 + 16);
                    MMA16816(ch[nt], a, b0, b1);
                    uint32_t c0 = *(const uint32_t*)(bBI + nt*8*SA + kc*32);
                    uint32_t c1 = *(const uint32_t*)(bBI + nt*8*SA + kc*32 + 16);
                    MMA16816(ci[nt], ai, c0, c1);
                }
            }
        }
        __syncthreads();
    }

    // ---- epilogue: gate math + state update ----
    const int m0 = mbase + wid*16 + l4;
    const int NT2 = l1 ? 1 : 2;
#pragma unroll
    for (int nt2 = 0; nt2 < 2; nt2++) {
        if (nt2 >= NT2) break;
        const int j = jbase + nt2*8 + lm4*2;
        // biases (pair loads)
        const float* bh = l1 ? bhh1 : bhh0;
        float2 bhr = *(const float2*)(bh + j);
        float2 bhz = *(const float2*)(bh + HH + j);
        float2 bhn = *(const float2*)(bh + 2*HH + j);
        float2 bir, biz, bin;
        if (l1) {
            bir = *(const float2*)(bih1 + j);
            biz = *(const float2*)(bih1 + HH + j);
            bin = *(const float2*)(bih1 + 2*HH + j);
        }
        const int rgate = nt2, zgate = l1 ? 1 : nt2+2, ngate = l1 ? 2 : nt2+4;
#pragma unroll
        for (int rr = 0; rr < 2; rr++) {
            const int m = m0 + rr*8;
            const bool keep = m < active;
            float gr0,gr1,gz0,gz1,gn0,gn1;
            if (!l1) {
                const float* gp = g_GI0 + (size_t)(t*BB + m)*G3;
                float2 a = *(const float2*)(gp + j);
                float2 b = *(const float2*)(gp + HH + j);
                float2 c = *(const float2*)(gp + 2*HH + j);
                gr0=a.x; gr1=a.y; gz0=b.x; gz1=b.y; gn0=c.x; gn1=c.y;
            } else {
                gr0 = ci[rgate][rr*2]   + bir.x;  gr1 = ci[rgate][rr*2+1] + bir.y;
                gz0 = ci[zgate][rr*2]   + biz.x;  gz1 = ci[zgate][rr*2+1] + biz.y;
                gn0 = ci[ngate][rr*2]   + bin.x;  gn1 = ci[ngate][rr*2+1] + bin.y;
            }
            float hr0 = ch[rgate][rr*2]   + bhr.x, hr1 = ch[rgate][rr*2+1] + bhr.y;
            float hz0 = ch[zgate][rr*2]   + bhz.x, hz1 = ch[zgate][rr*2+1] + bhz.y;
            float hn0 = ch[ngate][rr*2]   + bhn.x, hn1 = ch[ngate][rr*2+1] + bhn.y;

            size_t off = (size_t)m*HH + j;
            float2 hp = *(const float2*)(hpf_all + off);

            float r0 = sigf(gr0+hr0), z0 = sigf(gz0+hz0);
            float nv0 = tanhf(fmaf(r0, hn0, gn0));
            float hv0 = fmaf(z0, hp.x - nv0, nv0);
            float r1 = sigf(gr1+hr1), z1 = sigf(gz1+hz1);
            float nv1 = tanhf(fmaf(r1, hn1, gn1));
            float hv1 = fmaf(z1, hp.y - nv1, nv1);

            float kv0 = keep ? hv0 : hp.x;
            float kv1 = keep ? hv1 : hp.y;

            float2 outv; outv.x = kv0; outv.y = kv1;
            *(float2*)(hnf_all + off) = outv;
            __nv_bfloat162 vhi, vlo;
            split2(kv0, vhi.x, vlo.x);
            split2(kv1, vhi.y, vlo.y);
            *(__nv_bfloat162*)(hhi_all + off) = vhi;
            *(__nv_bfloat162*)(hlo_all + off) = vlo;
            if (!l1) {
                // layer1 input = UNMASKED hn
                __nv_bfloat162 xh, xl;
                split2(hv0, xh.x, xl.x);
                split2(hv1, xh.y, xl.y);
                *(__nv_bfloat162*)(g_x1hi[p] + off) = xh;
                *(__nv_bfloat162*)(g_x1lo[p] + off) = xl;
            }
        }
    }
}

// ---------------- final gather ----------------
__global__ void gather_kernel(const int* __restrict__ u, float* __restrict__ out) {
    int idx = blockIdx.x*blockDim.x + threadIdx.x;
    int l = idx / (BB*(HH/4));
    int rem = idx % (BB*(HH/4));
    int b = rem / (HH/4), j4 = rem % (HH/4);
    const float* src = (l ? g_h1f[0] : g_h0f[0]) + (size_t)u[b]*HH;
    ((float4*)out)[idx] = ((const float4*)src)[j4];
}

// ---------------------------------------------------------------------------
extern "C" void kernel_launch(void* const* d_in, const int* in_sizes, int n_in,
                              void* d_out, int out_size) {
    const float* x    = (const float*)d_in[0];
    const float* Wih0 = (const float*)d_in[1];
    const float* Whh0 = (const float*)d_in[2];
    const float* bih0 = (const float*)d_in[3];
    const float* bhh0 = (const float*)d_in[4];
    const float* Wih1 = (const float*)d_in[5];
    const float* Whh1 = (const float*)d_in[6];
    const float* bih1 = (const float*)d_in[7];
    const float* bhh1 = (const float*)d_in[8];
    const int*   bs   = (const int*)d_in[9];
    const int*   ui   = (const int*)d_in[10];

    zero_h_kernel<<<512, 256>>>();
    split_w_kernel<<<dim3((G3*HH)/256, 3), 256>>>(Whh0, Wih1, Whh1);
    gi0_kernel<<<dim3(48, 2*TT), 256>>>(x, Wih0, bih0, bs);
    for (int k = 0; k <= TT; k++)
        mma_step<<<384, 128>>>(bhh0, bih1, bhh1, bs, k);
    gather_kernel<<<256, 256>>>(ui, (float*)d_out);
}